// round 1
// baseline (speedup 1.0000x reference)
#include <cuda_runtime.h>
#include <cstdint>

#define NB 4913              // 17^3 triples
#define B_ 8
#define OHW 504
#define PLANE (OHW*OHW)      // 254016
#define NPIX (B_*PLANE)      // 2032128
#define CH 32

__device__ unsigned short g_triple[NPIX];
__device__ unsigned int   g_hist[NB];
__device__ float g_mean1[CH], g_rstd1[CH];
__device__ float g_mean2[CH], g_rstd2[CH];
__device__ __align__(16) float g_z1[NB*CH];
__device__ __align__(16) float g_lut[NB*CH];

// ---------------------------------------------------------------- zero hist
__global__ void k_zero_hist() {
    int i = blockIdx.x * blockDim.x + threadIdx.x;
    if (i < NB) g_hist[i] = 0u;
}

// ---------------------------------------------------------------- mode pool
// Packed 17-bin histogram: 5 u32 words, one byte per bin (bins 0..16).
__device__ __forceinline__ void padd(unsigned h[5], int b) {
    unsigned inc = 1u << ((b & 3) * 8);
    int w = b >> 2;
    h[0] += (w == 0) ? inc : 0u;
    h[1] += (w == 1) ? inc : 0u;
    h[2] += (w == 2) ? inc : 0u;
    h[3] += (w == 3) ? inc : 0u;
    h[4] += (w == 4) ? inc : 0u;
}

#define TY 8
#define TX 126
#define TXP (TX + 10)   // 136

__global__ __launch_bounds__(256) void k_mode(const float* __restrict__ x) {
    __shared__ unsigned char  sbin[TY + 10][TXP];       // 2448 B
    __shared__ unsigned int   scol[5][TY][TXP];         // 21760 B (SoA: conflict-free)
    __shared__ unsigned short strip[TY][TX];            // 2016 B
    __shared__ unsigned int   shist[NB];                // 19652 B

    int tid = threadIdx.x;
    int b   = blockIdx.z;
    int OY0 = blockIdx.y * TY;
    int OX0 = blockIdx.x * TX;

    for (int i = tid; i < NB; i += 256) shist[i] = 0u;

    const float* base = x + (size_t)b * 3 * 512 * 512;

    for (int c = 0; c < 3; c++) {
        __syncthreads();
        const float* plane = base + (size_t)c * 512 * 512;
        // load bins (padding -> bin 0, matching zero-pad then round)
        for (int i = tid; i < (TY + 10) * TXP; i += 256) {
            int iy = i / TXP, jx = i - iy * TXP;
            int gy = OY0 - 1 + iy, gx = OX0 - 1 + jx;
            unsigned char bn = 0;
            if (gy >= 0 && gy < 512 && gx >= 0 && gx < 512) {
                float v = plane[gy * 512 + gx];
                // exactly (x*255)/16 then round-half-even, like jnp
                int r = (int)rintf(__fmul_rn(v, 255.0f) * 0.0625f);
                r = max(0, min(16, r));
                bn = (unsigned char)r;
            }
            sbin[iy][jx] = bn;
        }
        __syncthreads();
        // column histograms over 11 rows
        for (int i = tid; i < TY * TXP; i += 256) {
            int yy = i / TXP, jx = i - yy * TXP;
            unsigned h[5] = {0, 0, 0, 0, 0};
            #pragma unroll
            for (int r = 0; r < 11; r++) padd(h, (int)sbin[yy + r][jx]);
            #pragma unroll
            for (int w = 0; w < 5; w++) scol[w][yy][jx] = h[w];
        }
        __syncthreads();
        // sliding window in x: 8 rows x 32 segments of 4
        {
            int yy = tid >> 5;
            int x0 = (tid & 31) * 4;
            if (x0 < TX) {
                unsigned h[5] = {0, 0, 0, 0, 0};
                #pragma unroll
                for (int j = 0; j < 11; j++) {
                    #pragma unroll
                    for (int w = 0; w < 5; w++) h[w] += scol[w][yy][x0 + j];
                }
                int xe = min(x0 + 4, TX);
                for (int xx = x0; xx < xe; xx++) {
                    // argmax, ascending bins, strict > => first-max like jnp.argmax
                    int best = -1, bbin = 0;
                    #pragma unroll
                    for (int bb = 0; bb < 17; bb++) {
                        int cnt = (int)((h[bb >> 2] >> ((bb & 3) * 8)) & 0xFFu);
                        if (cnt > best) { best = cnt; bbin = bb; }
                    }
                    if (c == 0)      strip[yy][xx] = (unsigned short)(bbin * 289);
                    else if (c == 1) strip[yy][xx] = (unsigned short)(strip[yy][xx] + bbin * 17);
                    else             strip[yy][xx] = (unsigned short)(strip[yy][xx] + bbin);
                    if (xx + 1 < xe) {
                        #pragma unroll
                        for (int w = 0; w < 5; w++)
                            h[w] += scol[w][yy][xx + 11] - scol[w][yy][xx];
                    }
                }
            }
        }
    }
    __syncthreads();
    size_t obase = ((size_t)b * OHW + OY0) * OHW + OX0;
    for (int i = tid; i < TY * TX; i += 256) {
        int yy = i / TX, xx = i - yy * TX;
        unsigned short t = strip[yy][xx];
        g_triple[obase + (size_t)yy * OHW + xx] = t;
        atomicAdd(&shist[t], 1u);
    }
    __syncthreads();
    for (int i = tid; i < NB; i += 256) {
        unsigned v = shist[i];
        if (v) atomicAdd(&g_hist[i], v);
    }
}

// ---------------------------------------------------------------- stage-1 BN stats
__global__ __launch_bounds__(256) void k_stats1(const float* __restrict__ w1, const float* __restrict__ b1,
                                                const float* __restrict__ wd1, const float* __restrict__ bd1) {
    int o = blockIdx.x, tid = threadIdx.x;
    float wa = w1[o * 3], wb = w1[o * 3 + 1], wc = w1[o * 3 + 2];
    float bb = b1[o], wdv = wd1[o], bdv = bd1[o];
    double s = 0.0, s2 = 0.0;
    for (int t = tid; t < NB; t += 256) {
        unsigned n = g_hist[t];
        if (!n) continue;
        int m0 = t / 289; int rem = t - m0 * 289; int m1 = rem / 17; int m2 = rem - m1 * 17;
        float y = (wa * (float)m0 + wb * (float)m1 + wc * (float)m2) * 0.0625f + bb;
        y = y * wdv + bdv;
        double yd = (double)y;
        s  += (double)n * yd;
        s2 += (double)n * yd * yd;
    }
    __shared__ double ss[256], sq[256];
    ss[tid] = s; sq[tid] = s2;
    __syncthreads();
    for (int st = 128; st > 0; st >>= 1) {
        if (tid < st) { ss[tid] += ss[tid + st]; sq[tid] += sq[tid + st]; }
        __syncthreads();
    }
    if (tid == 0) {
        double mean = ss[0] / (double)NPIX;
        double var  = sq[0] / (double)NPIX - mean * mean;
        if (var < 0.0) var = 0.0;
        g_mean1[o] = (float)mean;
        g_rstd1[o] = (float)(1.0 / sqrt(var + 1e-5));
    }
}

// ---------------------------------------------------------------- stage-1 activations per triple
__global__ void k_z1(const float* __restrict__ w1, const float* __restrict__ b1,
                     const float* __restrict__ wd1, const float* __restrict__ bd1,
                     const float* __restrict__ g1, const float* __restrict__ be1) {
    int t = blockIdx.x * blockDim.x + threadIdx.x;
    if (t >= NB) return;
    int m0 = t / 289; int rem = t - m0 * 289; int m1 = rem / 17; int m2 = rem - m1 * 17;
    #pragma unroll 4
    for (int o = 0; o < CH; o++) {
        float y = (w1[o * 3] * (float)m0 + w1[o * 3 + 1] * (float)m1 + w1[o * 3 + 2] * (float)m2) * 0.0625f + b1[o];
        y = y * wd1[o] + bd1[o];
        float z = (y - g_mean1[o]) * g_rstd1[o] * g1[o] + be1[o];
        z = (z >= 0.f) ? z : 0.01f * z;
        g_z1[t * CH + o] = z;
    }
}

// ---------------------------------------------------------------- stage-2 BN stats
__global__ __launch_bounds__(256) void k_stats2(const float* __restrict__ w2, const float* __restrict__ b2,
                                                const float* __restrict__ wd2, const float* __restrict__ bd2) {
    int o = blockIdx.x, tid = threadIdx.x;
    float wr[CH];
    #pragma unroll
    for (int c = 0; c < CH; c++) wr[c] = w2[o * CH + c];
    float bb = b2[o], wdv = wd2[o], bdv = bd2[o];
    double s = 0.0, s2 = 0.0;
    for (int t = tid; t < NB; t += 256) {
        unsigned n = g_hist[t];
        if (!n) continue;
        const float* z = &g_z1[t * CH];
        float acc = 0.f;
        #pragma unroll
        for (int c = 0; c < CH; c++) acc += wr[c] * z[c];
        float y = (acc + bb) * wdv + bdv;
        double yd = (double)y;
        s  += (double)n * yd;
        s2 += (double)n * yd * yd;
    }
    __shared__ double ss[256], sq[256];
    ss[tid] = s; sq[tid] = s2;
    __syncthreads();
    for (int st = 128; st > 0; st >>= 1) {
        if (tid < st) { ss[tid] += ss[tid + st]; sq[tid] += sq[tid + st]; }
        __syncthreads();
    }
    if (tid == 0) {
        double mean = ss[0] / (double)NPIX;
        double var  = sq[0] / (double)NPIX - mean * mean;
        if (var < 0.0) var = 0.0;
        g_mean2[o] = (float)mean;
        g_rstd2[o] = (float)(1.0 / sqrt(var + 1e-5));
    }
}

// ---------------------------------------------------------------- final 4913x32 LUT
__global__ __launch_bounds__(128) void k_lut(const float* __restrict__ w2, const float* __restrict__ b2,
                                             const float* __restrict__ wd2, const float* __restrict__ bd2,
                                             const float* __restrict__ g2, const float* __restrict__ be2) {
    int t = blockIdx.x * 4 + (threadIdx.x >> 5);
    int o = threadIdx.x & 31;
    if (t >= NB) return;
    const float* z = &g_z1[t * CH];
    float acc = 0.f;
    #pragma unroll
    for (int c = 0; c < CH; c++) acc += w2[o * CH + c] * z[c];
    float y = (acc + b2[o]) * wd2[o] + bd2[o];
    float zz = (y - g_mean2[o]) * g_rstd2[o] * g2[o] + be2[o];
    zz = (zz >= 0.f) ? zz : 0.01f * zz;
    g_lut[t * CH + o] = zz;
}

// ---------------------------------------------------------------- expand to [8,32,504,504]
__global__ __launch_bounds__(256) void k_expand(float* __restrict__ out) {
    int p = blockIdx.x * 256 + threadIdx.x;   // grid sized exactly to NPIX
    unsigned t = (unsigned)g_triple[p];
    const float4* row = reinterpret_cast<const float4*>(g_lut + (size_t)t * CH);
    float4 v[8];
    #pragma unroll
    for (int i = 0; i < 8; i++) v[i] = row[i];
    int b = p / PLANE;
    int r = p - b * PLANE;
    float* ob = out + (size_t)b * CH * PLANE + r;
    #pragma unroll
    for (int i = 0; i < 8; i++) {
        ob[(size_t)(4 * i + 0) * PLANE] = v[i].x;
        ob[(size_t)(4 * i + 1) * PLANE] = v[i].y;
        ob[(size_t)(4 * i + 2) * PLANE] = v[i].z;
        ob[(size_t)(4 * i + 3) * PLANE] = v[i].w;
    }
}

// ---------------------------------------------------------------- launch
extern "C" void kernel_launch(void* const* d_in, const int* in_sizes, int n_in,
                              void* d_out, int out_size) {
    const float* x   = (const float*)d_in[0];
    const float* w1  = (const float*)d_in[1];
    const float* b1  = (const float*)d_in[2];
    const float* wd1 = (const float*)d_in[3];
    const float* bd1 = (const float*)d_in[4];
    const float* g1  = (const float*)d_in[5];
    const float* be1 = (const float*)d_in[6];
    const float* w2  = (const float*)d_in[7];
    const float* b2  = (const float*)d_in[8];
    const float* wd2 = (const float*)d_in[9];
    const float* bd2 = (const float*)d_in[10];
    const float* g2  = (const float*)d_in[11];
    const float* be2 = (const float*)d_in[12];
    float* out = (float*)d_out;

    k_zero_hist<<<(NB + 255) / 256, 256>>>();
    k_mode<<<dim3(OHW / TX, OHW / TY, B_), 256>>>(x);
    k_stats1<<<CH, 256>>>(w1, b1, wd1, bd1);
    k_z1<<<(NB + 127) / 128, 128>>>(w1, b1, wd1, bd1, g1, be1);
    k_stats2<<<CH, 256>>>(w2, b2, wd2, bd2);
    k_lut<<<(NB + 3) / 4, 128>>>(w2, b2, wd2, bd2, g2, be2);
    k_expand<<<NPIX / 256, 256>>>(out);
}